// round 4
// baseline (speedup 1.0000x reference)
#include <cuda_runtime.h>
#include <cuda_bf16.h>
#include <stdint.h>

// Triangle scatter + symmetrize:
//   out[b, i, j] = (i == j) ? 0 : in[b, tri(max(i,j), min(i,j))]
//   tri(r, c) = r*(r-1)/2 + c
//
// BATCH = 32768, N = 64, NC2 = 2016. Pure data movement, HBM-bound.
// 4 batch rows per CTA, double-buffered smem, prefetch-to-register so the
// next row's LDGs overlap the current row's STGs. Index map (batch-invariant)
// computed once per CTA; diagonal handled via a dedicated zero slot in smem.

#define N_ATOMS 64
#define NC2     2016                 // 64*63/2
#define OUT_ROW (N_ATOMS * N_ATOMS)  // 4096
#define THREADS 256
#define ROWS    4                    // batch rows per CTA
#define SBUF    2032                 // 2016 data + 1 zero slot, padded to 16B mult

__global__ __launch_bounds__(THREADS)
void Triangle_39719857553609_kernel(const float* __restrict__ in,
                                    float* __restrict__ out,
                                    int batch) {
    __shared__ __align__(16) float s[2][SBUF];

    const int tid = threadIdx.x;
    const long b0 = (long)blockIdx.x * ROWS;

    // ---- Batch-invariant smem index map: 16 output elems per thread ----
    // Diagonal elements point at slot NC2, which holds 0.0f.
    int idx[16];
    #pragma unroll
    for (int k = 0; k < 4; k++) {
        const int q  = tid + k * THREADS;   // float4 index in [0,1024)
        const int i  = q >> 4;
        const int j0 = (q & 15) << 2;
        #pragma unroll
        for (int e = 0; e < 4; e++) {
            const int j  = j0 + e;
            const int hi = i > j ? i : j;
            const int lo = i > j ? j : i;
            idx[k * 4 + e] = (i == j) ? NC2 : (hi * (hi - 1)) / 2 + lo;
        }
    }

    // Zero slots (once; loads only ever write floats [0,2016))
    if (tid == 0) {
        s[0][NC2] = 0.0f;
        s[1][NC2] = 0.0f;
    }

    // ---- Prologue: load first row into buffer 0 ----
    // 2016 floats = 504 float4; threads 0..255 take t, threads 0..247 take t+256.
    {
        const float4* src = reinterpret_cast<const float4*>(in + b0 * NC2);
        float4* dst = reinterpret_cast<float4*>(s[0]);
        dst[tid] = src[tid];
        if (tid < 504 - THREADS) dst[tid + THREADS] = src[tid + THREADS];
    }
    __syncthreads();

    // ---- Pipelined main loop ----
    #pragma unroll
    for (int r = 0; r < ROWS; r++) {
        const bool more = (r + 1 < ROWS) && (b0 + r + 1 < batch);

        // Prefetch next row's input into registers (overlaps with stores below)
        float4 p0, p1;
        if (more) {
            const float4* nsrc =
                reinterpret_cast<const float4*>(in + (b0 + r + 1) * NC2);
            p0 = nsrc[tid];
            if (tid < 504 - THREADS) p1 = nsrc[tid + THREADS];
        }

        // Emit 64x64 output for current row from smem buffer r&1
        if (b0 + r < batch) {
            const float* sb = s[r & 1];
            float4* o4 = reinterpret_cast<float4*>(out + (b0 + r) * OUT_ROW);
            #pragma unroll
            for (int k = 0; k < 4; k++) {
                float4 v;
                v.x = sb[idx[k * 4 + 0]];
                v.y = sb[idx[k * 4 + 1]];
                v.z = sb[idx[k * 4 + 2]];
                v.w = sb[idx[k * 4 + 3]];
                o4[tid + k * THREADS] = v;
            }
        }

        // Commit prefetched registers into the other buffer
        if (more) {
            float4* dst = reinterpret_cast<float4*>(s[(r + 1) & 1]);
            dst[tid] = p0;
            if (tid < 504 - THREADS) dst[tid + THREADS] = p1;
        }
        __syncthreads();
    }
}

extern "C" void kernel_launch(void* const* d_in, const int* in_sizes, int n_in,
                              void* d_out, int out_size) {
    const float* in = (const float*)d_in[0];
    float* out = (float*)d_out;
    const int batch = in_sizes[0] / NC2;          // 32768
    const int grid  = (batch + ROWS - 1) / ROWS;  // 8192
    Triangle_39719857553609_kernel<<<grid, THREADS>>>(in, out, batch);
}

// round 6
// speedup vs baseline: 1.0263x; 1.0263x over previous
#include <cuda_runtime.h>
#include <cuda_bf16.h>
#include <stdint.h>

// Triangle scatter + symmetrize:
//   out[b, i, j] = (i == j) ? 0 : in[b, tri(max(i,j), min(i,j))]
//   tri(r, c) = r*(r-1)/2 + c
//
// BATCH = 32768, N = 64, NC2 = 2016. Pure data movement, HBM-bound.
// 2 batch rows per CTA, single barrier: both rows' inputs loaded up front
// (4 independent LDG.128 per thread = high MLP), then both output rows
// emitted from smem. Index map computed once, reused for both rows.
// Diagonal handled via a zero slot per buffer. Streaming cache hints on
// both touch-once streams.

#define N_ATOMS 64
#define NC2     2016                 // 64*63/2
#define OUT_ROW (N_ATOMS * N_ATOMS)  // 4096
#define THREADS 256
#define ROWS    2                    // batch rows per CTA
#define SBUF    2032                 // 2016 data + zero slot, 16B-padded

__global__ __launch_bounds__(THREADS)
void Triangle_39719857553609_kernel(const float* __restrict__ in,
                                    float* __restrict__ out) {
    __shared__ __align__(16) float s[ROWS][SBUF];

    const int tid = threadIdx.x;
    const long b0 = (long)blockIdx.x * ROWS;

    // ---- Load both rows' inputs (504 float4 each); 4 LDG in flight ----
    {
        const float4* src0 = reinterpret_cast<const float4*>(in + b0 * NC2);
        const float4* src1 = reinterpret_cast<const float4*>(in + (b0 + 1) * NC2);
        float4 a0, a1, b1, b2;
        bool tail = tid < (504 - THREADS);
        a0 = __ldcs(src0 + tid);
        b1 = __ldcs(src1 + tid);
        if (tail) {
            a1 = __ldcs(src0 + tid + THREADS);
            b2 = __ldcs(src1 + tid + THREADS);
        }
        float4* d0 = reinterpret_cast<float4*>(s[0]);
        float4* d1 = reinterpret_cast<float4*>(s[1]);
        d0[tid] = a0;
        d1[tid] = b1;
        if (tail) {
            d0[tid + THREADS] = a1;
            d1[tid + THREADS] = b2;
        }
    }

    // ---- Batch-invariant index map: 16 output elems per thread ----
    // Diagonal points at slot NC2 (zeroed below, before the barrier).
    int idx[16];
    #pragma unroll
    for (int k = 0; k < 4; k++) {
        const int q  = tid + k * THREADS;   // float4 index in [0,1024)
        const int i  = q >> 4;
        const int j0 = (q & 15) << 2;
        #pragma unroll
        for (int e = 0; e < 4; e++) {
            const int j  = j0 + e;
            const int hi = i > j ? i : j;
            const int lo = i > j ? j : i;
            idx[k * 4 + e] = (i == j) ? NC2 : (hi * (hi - 1)) / 2 + lo;
        }
    }

    if (tid == 0) {
        s[0][NC2] = 0.0f;
        s[1][NC2] = 0.0f;
    }
    __syncthreads();

    // ---- Emit both 64x64 output rows ----
    #pragma unroll
    for (int r = 0; r < ROWS; r++) {
        const float* sb = s[r];
        float4* o4 = reinterpret_cast<float4*>(out + (b0 + r) * OUT_ROW);
        #pragma unroll
        for (int k = 0; k < 4; k++) {
            float4 v;
            v.x = sb[idx[k * 4 + 0]];
            v.y = sb[idx[k * 4 + 1]];
            v.z = sb[idx[k * 4 + 2]];
            v.w = sb[idx[k * 4 + 3]];
            __stcs(o4 + tid + k * THREADS, v);
        }
    }
}

extern "C" void kernel_launch(void* const* d_in, const int* in_sizes, int n_in,
                              void* d_out, int out_size) {
    const float* in = (const float*)d_in[0];
    float* out = (float*)d_out;
    const int batch = in_sizes[0] / NC2;          // 32768 (even)
    const int grid  = batch / ROWS;               // 16384
    Triangle_39719857553609_kernel<<<grid, THREADS>>>(in, out);
}

// round 7
// speedup vs baseline: 1.0365x; 1.0099x over previous
#include <cuda_runtime.h>
#include <cuda_bf16.h>
#include <stdint.h>

// Triangle scatter + symmetrize:
//   out[b, i, j] = (i == j) ? 0 : in[b, tri(max(i,j), min(i,j))]
//   tri(r, c) = r*(r-1)/2 + c
//
// BATCH = 32768, N = 64, NC2 = 2016. Pure data movement, HBM-bound.
// 2 batch rows per CTA, single barrier: both rows' inputs loaded up front
// (4 independent LDG.128 per thread = high MLP), then both output rows
// emitted from smem. Index map computed once, reused for both rows.
// Diagonal handled via a zero slot per buffer. Streaming cache hints on
// both touch-once streams.

#define N_ATOMS 64
#define NC2     2016                 // 64*63/2
#define OUT_ROW (N_ATOMS * N_ATOMS)  // 4096
#define THREADS 256
#define ROWS    2                    // batch rows per CTA
#define SBUF    2032                 // 2016 data + zero slot, 16B-padded

__global__ __launch_bounds__(THREADS)
void Triangle_39719857553609_kernel(const float* __restrict__ in,
                                    float* __restrict__ out) {
    __shared__ __align__(16) float s[ROWS][SBUF];

    const int tid = threadIdx.x;
    const long b0 = (long)blockIdx.x * ROWS;

    // ---- Load both rows' inputs (504 float4 each); 4 LDG in flight ----
    {
        const float4* src0 = reinterpret_cast<const float4*>(in + b0 * NC2);
        const float4* src1 = reinterpret_cast<const float4*>(in + (b0 + 1) * NC2);
        float4 a0, a1, b1, b2;
        bool tail = tid < (504 - THREADS);
        a0 = __ldcs(src0 + tid);
        b1 = __ldcs(src1 + tid);
        if (tail) {
            a1 = __ldcs(src0 + tid + THREADS);
            b2 = __ldcs(src1 + tid + THREADS);
        }
        float4* d0 = reinterpret_cast<float4*>(s[0]);
        float4* d1 = reinterpret_cast<float4*>(s[1]);
        d0[tid] = a0;
        d1[tid] = b1;
        if (tail) {
            d0[tid + THREADS] = a1;
            d1[tid + THREADS] = b2;
        }
    }

    // ---- Batch-invariant index map: 16 output elems per thread ----
    // Diagonal points at slot NC2 (zeroed below, before the barrier).
    int idx[16];
    #pragma unroll
    for (int k = 0; k < 4; k++) {
        const int q  = tid + k * THREADS;   // float4 index in [0,1024)
        const int i  = q >> 4;
        const int j0 = (q & 15) << 2;
        #pragma unroll
        for (int e = 0; e < 4; e++) {
            const int j  = j0 + e;
            const int hi = i > j ? i : j;
            const int lo = i > j ? j : i;
            idx[k * 4 + e] = (i == j) ? NC2 : (hi * (hi - 1)) / 2 + lo;
        }
    }

    if (tid == 0) {
        s[0][NC2] = 0.0f;
        s[1][NC2] = 0.0f;
    }
    __syncthreads();

    // ---- Emit both 64x64 output rows ----
    #pragma unroll
    for (int r = 0; r < ROWS; r++) {
        const float* sb = s[r];
        float4* o4 = reinterpret_cast<float4*>(out + (b0 + r) * OUT_ROW);
        #pragma unroll
        for (int k = 0; k < 4; k++) {
            float4 v;
            v.x = sb[idx[k * 4 + 0]];
            v.y = sb[idx[k * 4 + 1]];
            v.z = sb[idx[k * 4 + 2]];
            v.w = sb[idx[k * 4 + 3]];
            __stcs(o4 + tid + k * THREADS, v);
        }
    }
}

extern "C" void kernel_launch(void* const* d_in, const int* in_sizes, int n_in,
                              void* d_out, int out_size) {
    const float* in = (const float*)d_in[0];
    float* out = (float*)d_out;
    const int batch = in_sizes[0] / NC2;          // 32768 (even)
    const int grid  = batch / ROWS;               // 16384
    Triangle_39719857553609_kernel<<<grid, THREADS>>>(in, out);
}